// round 1
// baseline (speedup 1.0000x reference)
#include <cuda_runtime.h>
#include <math.h>

#define H    1024
#define NL   2
#define NA   128
#define OP   16
#define G    32
#define NB   128          // blocks (all co-resident: >=148 SMs, 1 block/SM)
#define NT   256          // threads/block -> 8 warps -> 1024 warps total

// ---------------- persistent device state (no allocations allowed) ----------------
__device__ __align__(16) float g_h[2][2][2][H];   // [parity][substep][layer][j]
__device__ __align__(16) float g_c[2][2][2][H];
__device__ float g_ctx_logits[OP];
__device__ float g_left_logits[G];
__device__ float g_ent, g_lp;
__device__ unsigned g_count;                      // zero-initialized
__device__ volatile unsigned g_gen;

// ---------------- grid-wide barrier (sense-reversing, survives replays) -----------
__device__ __forceinline__ void grid_barrier() {
    __syncthreads();
    if (threadIdx.x == 0) {
        __threadfence();
        unsigned gen = g_gen;
        if (atomicAdd(&g_count, 1u) == NB - 1u) {
            g_count = 0u;
            __threadfence();
            g_gen = gen + 1u;
        } else {
            while (g_gen == gen) { }
            __threadfence();
        }
    }
    __syncthreads();
}

__device__ __forceinline__ float dot4(float4 a, float4 b) {
    return a.x * b.x + a.y * b.y + a.z * b.z + a.w * b.w;
}

__device__ __forceinline__ float warp_reduce(float v) {
#pragma unroll
    for (int o = 16; o; o >>= 1) v += __shfl_xor_sync(0xffffffffu, v, o);
    return v;
}

// stage 1024 floats into SMEM with NT=256 threads (1 float4 each)
__device__ __forceinline__ void stage_vec(float* dst, const float* src) {
    ((float4*)dst)[threadIdx.x] = ((const float4*)src)[threadIdx.x];
}
__device__ __forceinline__ void stage_zero(float* dst) {
    ((float4*)dst)[threadIdx.x] = make_float4(0.f, 0.f, 0.f, 0.f);
}

// one LSTM layer phase: warp j computes 4 gate dots (+hh dots) and finalizes unit j
__device__ __forceinline__ void lstm_phase(
    int j, int lane,
    const float* __restrict__ Wih, const float* __restrict__ Whh,
    const float* __restrict__ bih, const float* __restrict__ bhh,
    const float* x_s, const float* h_s,
    const float* __restrict__ cpre, bool zero_c,
    float* __restrict__ hout, float* __restrict__ cout)
{
    const float4* xv  = (const float4*)x_s;
    const float4* hv  = (const float4*)h_s;
    const float4* wi0 = (const float4*)(Wih + ((size_t)0 * H + j) * H);
    const float4* wi1 = (const float4*)(Wih + ((size_t)1 * H + j) * H);
    const float4* wi2 = (const float4*)(Wih + ((size_t)2 * H + j) * H);
    const float4* wi3 = (const float4*)(Wih + ((size_t)3 * H + j) * H);
    const float4* wh0 = (const float4*)(Whh + ((size_t)0 * H + j) * H);
    const float4* wh1 = (const float4*)(Whh + ((size_t)1 * H + j) * H);
    const float4* wh2 = (const float4*)(Whh + ((size_t)2 * H + j) * H);
    const float4* wh3 = (const float4*)(Whh + ((size_t)3 * H + j) * H);

    float a0 = 0.f, a1 = 0.f, a2 = 0.f, a3 = 0.f;
#pragma unroll
    for (int it = 0; it < 8; ++it) {
        int t = it * 32 + lane;
        float4 x4 = xv[t], h4 = hv[t];
        a0 += dot4(wi0[t], x4) + dot4(wh0[t], h4);
        a1 += dot4(wi1[t], x4) + dot4(wh1[t], h4);
        a2 += dot4(wi2[t], x4) + dot4(wh2[t], h4);
        a3 += dot4(wi3[t], x4) + dot4(wh3[t], h4);
    }
    a0 = warp_reduce(a0); a1 = warp_reduce(a1);
    a2 = warp_reduce(a2); a3 = warp_reduce(a3);

    if (lane == 0) {
        float zi = a0 + bih[0 * H + j] + bhh[0 * H + j];
        float zf = a1 + bih[1 * H + j] + bhh[1 * H + j];
        float zg = a2 + bih[2 * H + j] + bhh[2 * H + j];
        float zo = a3 + bih[3 * H + j] + bhh[3 * H + j];
        float ii = 1.f / (1.f + expf(-zi));
        float ff = 1.f / (1.f + expf(-zf));
        float gg = tanhf(zg);
        float oo = 1.f / (1.f + expf(-zo));
        float cp = zero_c ? 0.f : cpre[j];
        float cn = ff * cp + ii * gg;
        float hn = oo * tanhf(cn);
        cout[j] = cn;
        hout[j] = hn;
    }
}

// head row dot: weight row (global) . x (SMEM)
__device__ __forceinline__ float head_dot_s(const float* __restrict__ w,
                                            const float* x_s, int lane) {
    const float4* wv = (const float4*)w;
    const float4* xv = (const float4*)x_s;
    float a = 0.f;
#pragma unroll
    for (int it = 0; it < 8; ++it) { int t = it * 32 + lane; a += dot4(wv[t], xv[t]); }
    return warp_reduce(a);
}
// head row dot: weight row (global) . x (global)
__device__ __forceinline__ float head_dot_g(const float* __restrict__ w,
                                            const float* __restrict__ x, int lane) {
    const float4* wv = (const float4*)w;
    const float4* xv = (const float4*)x;
    float a = 0.f;
#pragma unroll
    for (int it = 0; it < 8; ++it) { int t = it * 32 + lane; a += dot4(wv[t], xv[t]); }
    return warp_reduce(a);
}

// single-thread log-softmax + entropy/log-prob accumulation (deterministic)
__device__ __forceinline__ void acc_softmax(const float* logits, int n,
                                            int chosen, float mask) {
    float m = -1e30f;
    for (int i = 0; i < n; ++i) m = fmaxf(m, logits[i]);
    float se = 0.f;
    for (int i = 0; i < n; ++i) se += expf(logits[i] - m);
    float lse = m + logf(se);
    float s = 0.f;
    for (int i = 0; i < n; ++i) { float ls = logits[i] - lse; s += expf(ls) * ls; }
    g_ent += mask * (-s);
    g_lp  += mask * (logits[chosen] - lse);
}

__global__ void __launch_bounds__(NT)
controller_kernel(const float* __restrict__ g_emb,
                  const float* __restrict__ W_ih, const float* __restrict__ W_hh,
                  const float* __restrict__ b_ih, const float* __restrict__ b_hh,
                  const float* __restrict__ ctx_W, const float* __restrict__ ctx_b,
                  const float* __restrict__ left_W, const float* __restrict__ left_b,
                  const int* __restrict__ config, const int* __restrict__ left_config,
                  float* __restrict__ out)
{
    __shared__ __align__(16) float x_s[H];
    __shared__ __align__(16) float h_s[H];

    const int tid  = threadIdx.x;
    const int lane = tid & 31;
    const int wid  = tid >> 5;
    const int W    = blockIdx.x * (NT / 32) + wid;   // global warp id == hidden unit j
    const int j    = W;

    if (blockIdx.x == 0 && tid == 0) { g_ent = 0.f; g_lp = 0.f; }

    const float* Wih0 = W_ih;
    const float* Wih1 = W_ih + (size_t)4 * H * H;
    const float* Whh0 = W_hh;
    const float* Whh1 = W_hh + (size_t)4 * H * H;
    const float* bih0 = b_ih;            const float* bih1 = b_ih + 4 * H;
    const float* bhh0 = b_hh;            const float* bhh1 = b_hh + 4 * H;

    for (int a = 0; a < NA; ++a) {
        const int  q     = a & 1;
        const int  p     = q ^ 1;
        const bool first = (a == 0);
        const int  sel   = (!first && config[a - 1] == 1) ? 1 : 0;

        // ---------- PHASE A: substep 0, layer 0 (+ left-head dots for step a-1) ----
        stage_vec(x_s, first ? g_emb : g_h[p][sel][1]);
        if (first) stage_zero(h_s); else stage_vec(h_s, g_h[p][sel][0]);
        __syncthreads();
        lstm_phase(j, lane, Wih0, Whh0, bih0, bhh0, x_s, h_s,
                   first ? (const float*)0 : g_c[p][sel][0], first,
                   g_h[q][0][0], g_c[q][0][0]);
        if (!first && (W & 31) == 0) {
            int r = W >> 5;                                   // 0..31
            float d = head_dot_g(left_W + ((size_t)(a - 1) * G + r) * H,
                                 g_h[p][1][1], lane);
            if (lane == 0) g_left_logits[r] = d + left_b[(a - 1) * G + r];
        }
        grid_barrier();

        // ---------- PHASE B: substep 0, layer 1 (+ left-head reduce for a-1) -------
        stage_vec(x_s, g_h[q][0][0]);
        if (first) stage_zero(h_s); else stage_vec(h_s, g_h[p][sel][1]);
        __syncthreads();
        lstm_phase(j, lane, Wih1, Whh1, bih1, bhh1, x_s, h_s,
                   first ? (const float*)0 : g_c[p][sel][1], first,
                   g_h[q][0][1], g_c[q][0][1]);
        if (!first && blockIdx.x == 0 && tid == 0)
            acc_softmax(g_left_logits, G, left_config[a - 1],
                        (config[a - 1] == 1) ? 1.f : 0.f);
        grid_barrier();

        // ---------- PHASE C: substep 1 (gap), layer 0 (+ ctx-head dots; x_s==out1) -
        stage_vec(x_s, g_h[q][0][1]);
        stage_vec(h_s, g_h[q][0][0]);
        __syncthreads();
        lstm_phase(j, lane, Wih0, Whh0, bih0, bhh0, x_s, h_s,
                   g_c[q][0][0], false, g_h[q][1][0], g_c[q][1][0]);
        if ((W & 63) == 0) {
            int r = W >> 6;                                   // 0..15
            float d = head_dot_s(ctx_W + ((size_t)a * OP + r) * H, x_s, lane);
            if (lane == 0) g_ctx_logits[r] = d + ctx_b[a * OP + r];
        }
        grid_barrier();

        // ---------- PHASE D: substep 1 (gap), layer 1 (+ ctx-head reduce) ----------
        stage_vec(x_s, g_h[q][1][0]);
        stage_vec(h_s, g_h[q][0][1]);
        __syncthreads();
        lstm_phase(j, lane, Wih1, Whh1, bih1, bhh1, x_s, h_s,
                   g_c[q][0][1], false, g_h[q][1][1], g_c[q][1][1]);
        if (blockIdx.x == 0 && tid == 0)
            acc_softmax(g_ctx_logits, OP, config[a], 1.f);
        grid_barrier();
    }

    // ---------- epilogue: left head for final step (a = 127, parity 1) -------------
    if ((W & 31) == 0) {
        int r = W >> 5;
        float d = head_dot_g(left_W + ((size_t)(NA - 1) * G + r) * H,
                             g_h[1][1][1], lane);
        if (lane == 0) g_left_logits[r] = d + left_b[(NA - 1) * G + r];
    }
    grid_barrier();
    if (blockIdx.x == 0 && tid == 0) {
        acc_softmax(g_left_logits, G, left_config[NA - 1],
                    (config[NA - 1] == 1) ? 1.f : 0.f);
        out[0] = g_ent;
        out[1] = g_lp;
    }
}

extern "C" void kernel_launch(void* const* d_in, const int* in_sizes, int n_in,
                              void* d_out, int out_size) {
    (void)in_sizes; (void)n_in; (void)out_size;
    const float* g_emb_p    = (const float*)d_in[0];
    const float* W_ih_p     = (const float*)d_in[1];
    const float* W_hh_p     = (const float*)d_in[2];
    const float* b_ih_p     = (const float*)d_in[3];
    const float* b_hh_p     = (const float*)d_in[4];
    const float* ctx_W_p    = (const float*)d_in[5];
    const float* ctx_b_p    = (const float*)d_in[6];
    const float* left_W_p   = (const float*)d_in[7];
    const float* left_b_p   = (const float*)d_in[8];
    const int*   config_p   = (const int*)d_in[9];
    const int*   left_cfg_p = (const int*)d_in[10];
    float* out = (float*)d_out;

    controller_kernel<<<NB, NT>>>(g_emb_p, W_ih_p, W_hh_p, b_ih_p, b_hh_p,
                                  ctx_W_p, ctx_b_p, left_W_p, left_b_p,
                                  config_p, left_cfg_p, out);
}

// round 4
// speedup vs baseline: 1.6446x; 1.6446x over previous
#include <cuda_runtime.h>
#include <math.h>

#define H    1024
#define NA   128
#define OP   16
#define G    32
#define NB   128          // blocks (co-resident on 148+ SMs)
#define NT   256          // 8 warps/block -> 1024 warps == 1024 hidden units

typedef unsigned long long ull;

#define QSCALE  327670.0f          // |w| < 0.1  ->  |q| <= 32767
#define QINV    (1.0f / 327670.0f)

// ---------------- persistent device state (no allocations allowed) ----------------
__device__ __align__(16) float g_h[2][2][2][H];   // [parity][substep][layer][j]
__device__ __align__(16) float g_c[2][2][2][H];
__device__ float g_ctx_logits[OP];
__device__ float g_left_logits[G];
__device__ float g_ent, g_lp;
__device__ volatile unsigned g_flags[NB];         // all-to-all barrier flags

// int16 weight scratch (filled by prep kernel every launch) + fused biases
__device__ __align__(32) short g_Wih_q[2u * 4u * H * H];   // 16.8 MB
__device__ __align__(32) short g_Whh_q[2u * 4u * H * H];   // 16.8 MB
__device__ __align__(16) float g_bsum[2 * 4 * H];

// ---------------- packed f32x2 helpers -------------------------------------------
__device__ __forceinline__ void fma2(ull& a, ull b, ull c) {
    asm("fma.rn.f32x2 %0, %1, %2, %0;" : "+l"(a) : "l"(b), "l"(c));
}
__device__ __forceinline__ ull pack2(float x, float y) {
    ull v; asm("mov.b64 %0, {%1, %2};" : "=l"(v) : "f"(x), "f"(y)); return v;
}
__device__ __forceinline__ float2 unpack2(ull v) {
    float2 f; asm("mov.b64 {%0, %1}, %2;" : "=f"(f.x), "=f"(f.y) : "l"(v)); return f;
}
// two int16 -> packed f32x2
__device__ __forceinline__ ull s2f2(unsigned u) {
    float a, b;
    asm("{\n\t"
        ".reg .b16 lo, hi;\n\t"
        "mov.b32 {lo, hi}, %2;\n\t"
        "cvt.rn.f32.s16 %0, lo;\n\t"
        "cvt.rn.f32.s16 %1, hi;\n\t"
        "}" : "=f"(a), "=f"(b) : "r"(u));
    return pack2(a, b);
}

// 32-byte weight load pinned to L2 (evict_last requires .v4.b64 on sm_103a)
struct U8w { unsigned u[8]; };
__device__ __forceinline__ U8w ldg_el32(const void* p) {
    ull r0, r1, r2, r3;
    asm("ld.global.nc.L2::evict_last.v4.b64 {%0,%1,%2,%3}, [%4];"
        : "=l"(r0), "=l"(r1), "=l"(r2), "=l"(r3) : "l"(p));
    U8w v;
    asm("mov.b64 {%0,%1}, %2;" : "=r"(v.u[0]), "=r"(v.u[1]) : "l"(r0));
    asm("mov.b64 {%0,%1}, %2;" : "=r"(v.u[2]), "=r"(v.u[3]) : "l"(r1));
    asm("mov.b64 {%0,%1}, %2;" : "=r"(v.u[4]), "=r"(v.u[5]) : "l"(r2));
    asm("mov.b64 {%0,%1}, %2;" : "=r"(v.u[6]), "=r"(v.u[7]) : "l"(r3));
    return v;
}

__device__ __forceinline__ float warp_reduce(float v) {
#pragma unroll
    for (int o = 16; o; o >>= 1) v += __shfl_xor_sync(0xffffffffu, v, o);
    return v;
}
__device__ __forceinline__ float dot4(float4 a, float4 b) {
    return a.x * b.x + a.y * b.y + a.z * b.z + a.w * b.w;
}

// ---------------- all-to-all grid barrier (flag per block, replay-safe) -----------
__device__ __forceinline__ void grid_barrier(unsigned target, int lane) {
    __threadfence();
    __syncthreads();
    if (threadIdx.x == 0) g_flags[blockIdx.x] = target;
    if (threadIdx.x < 32) {
        for (;;) {
            unsigned f0 = g_flags[lane];
            unsigned f1 = g_flags[lane + 32];
            unsigned f2 = g_flags[lane + 64];
            unsigned f3 = g_flags[lane + 96];
            bool ok = ((int)(f0 - target) >= 0) && ((int)(f1 - target) >= 0) &&
                      ((int)(f2 - target) >= 0) && ((int)(f3 - target) >= 0);
            if (__all_sync(0xffffffffu, ok)) break;
        }
        __threadfence();
    }
    __syncthreads();
}

// stage 1024 floats into SMEM with 256 threads (1 float4 each)
__device__ __forceinline__ void stage_vec(float* dst, const float* src) {
    ((float4*)dst)[threadIdx.x] = ((const float4*)src)[threadIdx.x];
}
__device__ __forceinline__ void stage_zero(float* dst) {
    ((float4*)dst)[threadIdx.x] = make_float4(0.f, 0.f, 0.f, 0.f);
}

// one LSTM layer phase with int16 weights, f32x2 packed FMA.
// warp j computes 4 (ih + hh) gate dots and finalizes unit j.
__device__ __forceinline__ void lstm_phase(
    int j, int lane,
    const short* __restrict__ Wih, const short* __restrict__ Whh, // layer bases
    const float* __restrict__ bsum,                               // layer base
    const float* x_s, const float* h_s,
    const float* __restrict__ cpre, bool zero_c,
    float* __restrict__ hout, float* __restrict__ cout)
{
    const char* wr[8];
#pragma unroll
    for (int g = 0; g < 4; ++g) {
        wr[g]     = (const char*)(Wih + ((size_t)g * H + j) * H);
        wr[g + 4] = (const char*)(Whh + ((size_t)g * H + j) * H);
    }
    const float4* xv = (const float4*)x_s;
    const float4* hv = (const float4*)h_s;

    ull acc[8] = {0, 0, 0, 0, 0, 0, 0, 0};   // bit pattern 0 == (0.0f, 0.0f)

#pragma unroll
    for (int it = 0; it < 2; ++it) {
        const int t = it * 32 + lane;          // 32B chunk index, 0..63 (16 cols each)
        U8w w[8];
#pragma unroll
        for (int r = 0; r < 8; ++r) w[r] = ldg_el32(wr[r] + (size_t)t * 32);

        // x/h columns [16t, 16t+16): 4 float4 each -> 8 packed f32x2 each
        ull xp[8], hp[8];
#pragma unroll
        for (int k = 0; k < 4; ++k) {
            float4 x4 = xv[4 * t + k];
            float4 h4 = hv[4 * t + k];
            xp[2 * k]     = pack2(x4.x, x4.y);
            xp[2 * k + 1] = pack2(x4.z, x4.w);
            hp[2 * k]     = pack2(h4.x, h4.y);
            hp[2 * k + 1] = pack2(h4.z, h4.w);
        }

#pragma unroll
        for (int r = 0; r < 4; ++r)
#pragma unroll
            for (int k = 0; k < 8; ++k)
                fma2(acc[r], s2f2(w[r].u[k]), xp[k]);
#pragma unroll
        for (int r = 4; r < 8; ++r)
#pragma unroll
            for (int k = 0; k < 8; ++k)
                fma2(acc[r], s2f2(w[r].u[k]), hp[k]);
    }

    float gate[4];
#pragma unroll
    for (int g = 0; g < 4; ++g) {
        float2 a = unpack2(acc[g]);
        float2 b = unpack2(acc[g + 4]);
        gate[g] = warp_reduce((a.x + a.y) + (b.x + b.y));
    }

    if (lane == 0) {
        float zi = gate[0] * QINV + bsum[0 * H + j];
        float zf = gate[1] * QINV + bsum[1 * H + j];
        float zg = gate[2] * QINV + bsum[2 * H + j];
        float zo = gate[3] * QINV + bsum[3 * H + j];
        float ii = 1.f / (1.f + expf(-zi));
        float ff = 1.f / (1.f + expf(-zf));
        float gg = tanhf(zg);
        float oo = 1.f / (1.f + expf(-zo));
        float cp = zero_c ? 0.f : cpre[j];
        float cn = ff * cp + ii * gg;
        float hn = oo * tanhf(cn);
        cout[j] = cn;
        hout[j] = hn;
    }
}

// head row dot: fp32 weight row (global, streaming) . x (SMEM or global)
__device__ __forceinline__ float head_dot(const float* __restrict__ w,
                                          const float* x, int lane) {
    const float4* wv = (const float4*)w;
    const float4* xv = (const float4*)x;
    float a = 0.f;
#pragma unroll
    for (int it = 0; it < 8; ++it) {
        int t = it * 32 + lane;
        a += dot4(__ldcs(wv + t), xv[t]);
    }
    return warp_reduce(a);
}

// single-thread log-softmax + entropy/log-prob accumulation (deterministic)
__device__ __forceinline__ void acc_softmax(const float* logits, int n,
                                            int chosen, float mask) {
    float m = -1e30f;
    for (int i = 0; i < n; ++i) m = fmaxf(m, logits[i]);
    float se = 0.f;
    for (int i = 0; i < n; ++i) se += expf(logits[i] - m);
    float lse = m + logf(se);
    float s = 0.f;
    for (int i = 0; i < n; ++i) { float ls = logits[i] - lse; s += expf(ls) * ls; }
    g_ent += mask * (-s);
    g_lp  += mask * (logits[chosen] - lse);
}

// ---------------- prep kernels (run every launch; deterministic) ------------------
__global__ void __launch_bounds__(256)
convert_kernel(const float* __restrict__ Wih, const float* __restrict__ Whh) {
    const size_t N4 = (size_t)2 * 4 * H * H / 4;   // float4 count per tensor
    size_t i = (size_t)blockIdx.x * blockDim.x + threadIdx.x;
    float4 v;
    short4* dst;
    if (i < N4) {
        v   = __ldcs((const float4*)Wih + i);      // streaming: don't pollute L2
        dst = (short4*)(g_Wih_q + i * 4);
    } else {
        size_t k = i - N4;
        v   = __ldcs((const float4*)Whh + k);
        dst = (short4*)(g_Whh_q + k * 4);
    }
    short4 q;
    q.x = (short)__float2int_rn(v.x * QSCALE);
    q.y = (short)__float2int_rn(v.y * QSCALE);
    q.z = (short)__float2int_rn(v.z * QSCALE);
    q.w = (short)__float2int_rn(v.w * QSCALE);
    *dst = q;
}

__global__ void __launch_bounds__(256)
bias_kernel(const float* __restrict__ bih, const float* __restrict__ bhh) {
    int i = blockIdx.x * blockDim.x + threadIdx.x;   // 0..8191
    g_bsum[i] = bih[i] + bhh[i];
}

// ---------------- main persistent kernel ------------------------------------------
__global__ void __launch_bounds__(NT, 1)
controller_kernel(const float* __restrict__ g_emb,
                  const float* __restrict__ ctx_W, const float* __restrict__ ctx_b,
                  const float* __restrict__ left_W, const float* __restrict__ left_b,
                  const int* __restrict__ config, const int* __restrict__ left_config,
                  float* __restrict__ out)
{
    __shared__ __align__(16) float x_s[H];
    __shared__ __align__(16) float h_s[H];
    __shared__ unsigned s_base;

    const int tid  = threadIdx.x;
    const int lane = tid & 31;
    const int wid  = tid >> 5;
    const int W    = blockIdx.x * (NT / 32) + wid;   // global warp id == hidden unit j
    const int j    = W;

    if (tid == 0) s_base = g_flags[blockIdx.x];      // replay-safe barrier epoch base
    if (blockIdx.x == 0 && tid == 0) { g_ent = 0.f; g_lp = 0.f; }
    __syncthreads();
    unsigned bar = s_base;

    const short* Wih0 = g_Wih_q;
    const short* Wih1 = g_Wih_q + (size_t)4 * H * H;
    const short* Whh0 = g_Whh_q;
    const short* Whh1 = g_Whh_q + (size_t)4 * H * H;
    const float* bs0  = g_bsum;
    const float* bs1  = g_bsum + 4 * H;

    for (int a = 0; a < NA; ++a) {
        const int  q     = a & 1;
        const int  p     = q ^ 1;
        const bool first = (a == 0);
        const int  sel   = (!first && config[a - 1] == 1) ? 1 : 0;

        // ---- PHASE A: substep 0, layer 0 (+ left-head dots for step a-1) ----------
        stage_vec(x_s, first ? g_emb : g_h[p][sel][1]);
        if (first) stage_zero(h_s); else stage_vec(h_s, g_h[p][sel][0]);
        __syncthreads();
        lstm_phase(j, lane, Wih0, Whh0, bs0, x_s, h_s,
                   first ? (const float*)0 : g_c[p][sel][0], first,
                   g_h[q][0][0], g_c[q][0][0]);
        if (!first && (W & 31) == 0) {
            int r = W >> 5;                                   // 0..31
            float d = head_dot(left_W + ((size_t)(a - 1) * G + r) * H,
                               g_h[p][1][1], lane);
            if (lane == 0) g_left_logits[r] = d + left_b[(a - 1) * G + r];
        }
        grid_barrier(++bar, lane);

        // ---- PHASE B: substep 0, layer 1 (+ left-head reduce for a-1) -------------
        stage_vec(x_s, g_h[q][0][0]);
        if (first) stage_zero(h_s); else stage_vec(h_s, g_h[p][sel][1]);
        __syncthreads();
        lstm_phase(j, lane, Wih1, Whh1, bs1, x_s, h_s,
                   first ? (const float*)0 : g_c[p][sel][1], first,
                   g_h[q][0][1], g_c[q][0][1]);
        if (!first && blockIdx.x == 0 && tid == 0)
            acc_softmax(g_left_logits, G, left_config[a - 1],
                        (config[a - 1] == 1) ? 1.f : 0.f);
        grid_barrier(++bar, lane);

        // ---- PHASE C: substep 1 (gap), layer 0 (+ ctx-head dots; x_s == out1) -----
        stage_vec(x_s, g_h[q][0][1]);
        stage_vec(h_s, g_h[q][0][0]);
        __syncthreads();
        lstm_phase(j, lane, Wih0, Whh0, bs0, x_s, h_s,
                   g_c[q][0][0], false, g_h[q][1][0], g_c[q][1][0]);
        if ((W & 63) == 0) {
            int r = W >> 6;                                   // 0..15
            float d = head_dot(ctx_W + ((size_t)a * OP + r) * H, x_s, lane);
            if (lane == 0) g_ctx_logits[r] = d + ctx_b[a * OP + r];
        }
        grid_barrier(++bar, lane);

        // ---- PHASE D: substep 1 (gap), layer 1 (+ ctx-head reduce) ----------------
        stage_vec(x_s, g_h[q][1][0]);
        stage_vec(h_s, g_h[q][0][1]);
        __syncthreads();
        lstm_phase(j, lane, Wih1, Whh1, bs1, x_s, h_s,
                   g_c[q][0][1], false, g_h[q][1][1], g_c[q][1][1]);
        if (blockIdx.x == 0 && tid == 0)
            acc_softmax(g_ctx_logits, OP, config[a], 1.f);
        grid_barrier(++bar, lane);
    }

    // ---- epilogue: left head for final step (a = 127, parity 1) -------------------
    if ((W & 31) == 0) {
        int r = W >> 5;
        float d = head_dot(left_W + ((size_t)(NA - 1) * G + r) * H,
                           g_h[1][1][1], lane);
        if (lane == 0) g_left_logits[r] = d + left_b[(NA - 1) * G + r];
    }
    grid_barrier(++bar, lane);
    if (blockIdx.x == 0 && tid == 0) {
        acc_softmax(g_left_logits, G, left_config[NA - 1],
                    (config[NA - 1] == 1) ? 1.f : 0.f);
        out[0] = g_ent;
        out[1] = g_lp;
    }
}

extern "C" void kernel_launch(void* const* d_in, const int* in_sizes, int n_in,
                              void* d_out, int out_size) {
    (void)in_sizes; (void)n_in; (void)out_size;
    const float* g_emb_p    = (const float*)d_in[0];
    const float* W_ih_p     = (const float*)d_in[1];
    const float* W_hh_p     = (const float*)d_in[2];
    const float* b_ih_p     = (const float*)d_in[3];
    const float* b_hh_p     = (const float*)d_in[4];
    const float* ctx_W_p    = (const float*)d_in[5];
    const float* ctx_b_p    = (const float*)d_in[6];
    const float* left_W_p   = (const float*)d_in[7];
    const float* left_b_p   = (const float*)d_in[8];
    const int*   config_p   = (const int*)d_in[9];
    const int*   left_cfg_p = (const int*)d_in[10];
    float* out = (float*)d_out;

    // int16 weight conversion: 2 tensors x (2*4*H*H/4) float4 threads
    const size_t N4 = (size_t)2 * 4 * H * H / 4;           // 2,097,152 per tensor
    const int conv_blocks = (int)((2 * N4 + 255) / 256);   // 16384
    convert_kernel<<<conv_blocks, 256>>>(W_ih_p, W_hh_p);
    bias_kernel<<<(2 * 4 * H) / 256, 256>>>(b_ih_p, b_hh_p);

    controller_kernel<<<NB, NT>>>(g_emb_p, ctx_W_p, ctx_b_p, left_W_p, left_b_p,
                                  config_p, left_cfg_p, out);
}